// round 14
// baseline (speedup 1.0000x reference)
#include <cuda_runtime.h>
#include <cuda_fp16.h>
#include <math.h>

#define BB   64
#define VV   2048
#define ENCD 128
#define TT   100
#define EMBD 256
#define DECD 512
#define ATTD 256
#define NVOC 29
#define XD   384   // EMB + ENC
#define NCH  16    // V-chunks of 128
#define NG   2048  // 4*DEC gate rows
#define KZ   896   // XD + DECD
#define NKC  7     // k-chunks of 128

#define PRED_OFF  0
#define ALPHA_OFF (BB*TT*NVOC)            // 185600
#define LEN_OFF   (ALPHA_OFF + BB*TT*VV)  // 13292800

// ---------------- scratch (device globals; no allocation allowed) ----------
__device__ __half g_enc_att_h[BB*VV*ATTD];  // 64 MB fp16
__device__ __half g_enc_h[BB*VV*ENCD];      // 32 MB fp16
__device__ __half g_wz[NG*KZ];              // 3.7 MB merged fp16 [emb|awe|h]
__device__ float  g_bz[NG];                 // merged bias
__device__ float  g_gpart[NKC*BB*NG];       // gate partials [kc][b][row]
__device__ float  g_h[BB*DECD];
__device__ float  g_c[BB*DECD];             // single c (finisher block owns b)
__device__ float  g_dec_att[BB*ATTD];
__device__ float  g_gate[BB*ENCD];
__device__ float  g_part[BB*NCH*ENCD];      // partial awe [b][chunk][d]
__device__ float  g_psum[BB*NCH];           // partial expsum
__device__ int    g_cnt1[BB];               // finisher counters (self-resetting)

__device__ __forceinline__ float sigf(float x) { return 1.f/(1.f+__expf(-x)); }

// ============================================================================
// Setup A: mean_enc -> h0,c0 ; heads(h0) for step 0 ; lengths to out tail
// ============================================================================
__global__ void s_init(const float* __restrict__ enc, const int* __restrict__ lens,
                       const float* __restrict__ Wih_, const float* __restrict__ bih_,
                       const float* __restrict__ Wic_, const float* __restrict__ bic_,
                       const float* __restrict__ Wdec, const float* __restrict__ bdec,
                       const float* __restrict__ Wbeta, const float* __restrict__ bbeta,
                       float* __restrict__ out)
{
    int b = blockIdx.x, tid = threadIdx.x;
    __shared__ __align__(16) float red[16*128];
    __shared__ __align__(16) float mean[128];
    __shared__ __align__(16) float hs[512];
    int vr = tid >> 5, l = tid & 31;

    float4 acc = make_float4(0.f,0.f,0.f,0.f);
    for (int v = vr; v < VV; v += 16) {
        float4 e = *(const float4*)&enc[((size_t)(b*VV + v))*ENCD + l*4];
        acc.x += e.x; acc.y += e.y; acc.z += e.z; acc.w += e.w;
    }
    *(float4*)&red[vr*128 + l*4] = acc;
    __syncthreads();
    if (tid < 128) {
        float s = 0.f;
        #pragma unroll
        for (int i = 0; i < 16; i++) s += red[i*128 + tid];
        mean[tid] = s * (1.f/(float)VV);
    }
    __syncthreads();
    float ha = bih_[tid], ca = bic_[tid];
    const float* wh = Wih_ + (size_t)tid*ENCD;
    const float* wc = Wic_ + (size_t)tid*ENCD;
    #pragma unroll 4
    for (int k = 0; k < ENCD; k++) {
        float mk = mean[k];
        ha += mk * wh[k];
        ca += mk * wc[k];
    }
    g_h[b*DECD + tid] = ha;
    g_c[b*DECD + tid] = ca;
    hs[tid] = ha;
    if (tid == 0) out[LEN_OFF + b] = (float)lens[b];
    __syncthreads();

    int sub = tid & 3, g = tid >> 2;
    #pragma unroll
    for (int pass = 0; pass < 3; pass++) {
        int row = pass*128 + g;
        const float* wrow; float bias; int kind;
        if (row < 256) { wrow = Wdec  + (size_t)row*DECD;       bias = bdec[row];       kind = 0; }
        else           { wrow = Wbeta + (size_t)(row-256)*DECD; bias = bbeta[row-256];  kind = 1; }
        float a = 0.f;
        #pragma unroll 8
        for (int i = 0; i < 32; i++) {
            int k = sub*4 + i*16;
            float4 w  = *(const float4*)&wrow[k];
            float4 hz = *(const float4*)&hs[k];
            a += w.x*hz.x + w.y*hz.y + w.z*hz.z + w.w*hz.w;
        }
        a += __shfl_xor_sync(0xffffffffu, a, 1);
        a += __shfl_xor_sync(0xffffffffu, a, 2);
        if (sub == 0) {
            a += bias;
            if (kind == 0) g_dec_att[b*ATTD + row] = a;
            else           g_gate[b*ENCD + (row-256)] = sigf(a);
        }
    }
}

// ============================================================================
// Setup W: merge LSTM weights to fp16 [row][XD | DECD], merged bias
// ============================================================================
__global__ void s_wlstm(const float* __restrict__ Wih, const float* __restrict__ bih,
                        const float* __restrict__ Whh, const float* __restrict__ bhh)
{
    int row = blockIdx.x, tid = threadIdx.x;
    for (int k = tid; k < XD; k += 256)
        g_wz[(size_t)row*KZ + k] = __float2half_rn(Wih[(size_t)row*XD + k]);
    for (int k = tid; k < DECD; k += 256)
        g_wz[(size_t)row*KZ + XD + k] = __float2half_rn(Whh[(size_t)row*DECD + k]);
    if (tid == 0) g_bz[row] = bih[row] + bhh[row];
}

// ============================================================================
// Setup B: enc_att(fp16) = enc @ W_enc.T + b_enc ; fp16 enc copy
// ============================================================================
#define EA_SMEM ((128*264 + 128*68)*4)
__global__ void __launch_bounds__(256)
s_encatt(const float* __restrict__ enc, const float* __restrict__ Wenc,
         const float* __restrict__ benc)
{
    extern __shared__ float sm[];
    float* Wt = sm;             // [128][264]
    float* Et = sm + 128*264;   // [128][68]
    int tid = threadIdx.x;
    int rowbase = blockIdx.x * 32;

    for (int i = tid; i < 256*128; i += 256) {
        int k = i & 127, a = i >> 7;
        Wt[k*264 + a] = Wenc[a*128 + k];
    }
    for (int i = tid; i < 32*128; i += 256) {
        int k = i & 127, r = i >> 7;
        Et[k*68 + r] = enc[(size_t)(rowbase + r)*128 + k];
    }
    __syncthreads();

    for (int i = tid; i < 32*128; i += 256) {
        int r = i >> 7, k = i & 127;
        g_enc_h[(size_t)(rowbase + r)*ENCD + k] = __float2half_rn(Et[k*68 + r]);
    }

    int tr = tid >> 5, ta = tid & 31;
    int r0 = tr*4, a0 = ta*8;
    float acc[4][8];
    #pragma unroll
    for (int i = 0; i < 4; i++)
        #pragma unroll
        for (int j = 0; j < 8; j++) acc[i][j] = 0.f;

    #pragma unroll 4
    for (int k = 0; k < 128; k++) {
        float4 rf = *(const float4*)&Et[k*68 + r0];
        float4 a4 = *(const float4*)&Wt[k*264 + a0];
        float4 b4 = *(const float4*)&Wt[k*264 + a0 + 4];
        float rr[4] = {rf.x, rf.y, rf.z, rf.w};
        float aa[8] = {a4.x,a4.y,a4.z,a4.w,b4.x,b4.y,b4.z,b4.w};
        #pragma unroll
        for (int i = 0; i < 4; i++)
            #pragma unroll
            for (int j = 0; j < 8; j++) acc[i][j] += rr[i]*aa[j];
    }
    float4 be0 = *(const float4*)&benc[a0];
    float4 be1 = *(const float4*)&benc[a0+4];
    float bb[8] = {be0.x,be0.y,be0.z,be0.w,be1.x,be1.y,be1.z,be1.w};
    #pragma unroll
    for (int i = 0; i < 4; i++) {
        size_t base = (size_t)(rowbase + r0 + i)*ATTD + a0;
        __half2 h[4];
        #pragma unroll
        for (int j = 0; j < 4; j++)
            h[j] = __floats2half2_rn(acc[i][2*j] + bb[2*j], acc[i][2*j+1] + bb[2*j+1]);
        *(uint4*)&g_enc_att_h[base] = *(uint4*)h;
    }
}

// ============================================================================
// k6a: split-K LSTM GEMM for kc in {0,1,3,4,5,6}.  grid(6, 32), block 256.
// Launched BEFORE kB each step (needs only h(t-1)); kc=2 done by kB finisher.
// ============================================================================
__global__ void __launch_bounds__(256)
k6a_gemm(int t, const int* __restrict__ lens,
         const int* __restrict__ captions, const float* __restrict__ embW)
{
    int m = blockIdx.x, rc = blockIdx.y, tid = threadIdx.x;
    int kcReal = (m < 2) ? m : m + 1;      // skip kc=2 (awe)
    __shared__ __align__(16) float wt[128*68];   // [k][r]
    __shared__ __align__(16) float zt[128*68];   // [k][b]
    __shared__ int   caps[64];

    int pred = (tid < 64) && (t < lens[tid]);
    int nb = __syncthreads_count(pred);
    if (nb == 0) return;

    int kbase = kcReal * 128;
    int rowbase = rc * 64;

    if (kcReal < 2 && tid < 64) caps[tid] = captions[tid*TT + t];
    __syncthreads();

    for (int i = tid; i < 64*64; i += 256) {
        int r = i >> 6, kp = i & 63;
        unsigned int u = *(const unsigned int*)&g_wz[(size_t)(rowbase + r)*KZ + kbase + kp*2];
        float2 f = __half22float2(*(const __half2*)&u);
        wt[(kp*2  )*68 + r] = f.x;
        wt[(kp*2+1)*68 + r] = f.y;
    }
    if (kcReal < 2) {
        for (int i = tid; i < 64*128; i += 256) {
            int b = i >> 7, k = i & 127;
            zt[k*68 + b] = embW[(size_t)caps[b]*EMBD + kbase + k];
        }
    } else {
        for (int i = tid; i < 64*128; i += 256) {
            int b = i >> 7, k = i & 127;
            zt[k*68 + b] = g_h[b*DECD + (kbase - XD) + k];
        }
    }
    __syncthreads();

    int r0 = (tid & 15) * 4;
    int b0 = (tid >> 4) * 4;
    if (b0 >= nb) return;

    float acc[4][4];
    #pragma unroll
    for (int i = 0; i < 4; i++)
        #pragma unroll
        for (int j = 0; j < 4; j++) acc[i][j] = 0.f;

    #pragma unroll 4
    for (int k = 0; k < 128; k++) {
        float4 w = *(const float4*)&wt[k*68 + r0];
        float4 z = *(const float4*)&zt[k*68 + b0];
        float ww[4] = {w.x, w.y, w.z, w.w};
        float zz[4] = {z.x, z.y, z.z, z.w};
        #pragma unroll
        for (int i = 0; i < 4; i++)
            #pragma unroll
            for (int j = 0; j < 4; j++) acc[i][j] += ww[i]*zz[j];
    }
    #pragma unroll
    for (int j = 0; j < 4; j++) {
        *(float4*)&g_gpart[((size_t)(kcReal*BB + b0 + j))*NG + rowbase + r0] =
            make_float4(acc[0][j], acc[1][j], acc[2][j], acc[3][j]);
    }
}

// ============================================================================
// Finisher (noinline keeps the streamer's register allocation tight; all
// shared buffers it touches are declared __align__(16) at the caller).
//   awe + alpha-normalize -> kc=2 GEMV -> cell (c,h) -> heads
// ============================================================================
__device__ __noinline__ void kb_finisher(
    int b, int t, int tid,
    const float* __restrict__ Wdec, const float* __restrict__ bdec,
    const float* __restrict__ Wbeta, const float* __restrict__ bbeta,
    const float* __restrict__ Wfin, const float* __restrict__ bfin,
    float* __restrict__ out, float* aw, float* hn)
{
    // acquire: make all chunk blocks' g_part/g_psum/alpha writes visible
    __threadfence();

    float S = 0.f;
    #pragma unroll 1
    for (int i = 0; i < NCH; i++) S += __ldcg(&g_psum[b*NCH + i]);
    float invS = 1.f/S;

    // awe (gated)
    if (tid < 128) {
        float s = 0.f;
        #pragma unroll 1
        for (int ch = 0; ch < NCH; ch++)
            s += __ldcg(&g_part[(b*NCH + ch)*ENCD + tid]);
        aw[tid] = s * invS * __ldcg(&g_gate[b*ENCD + tid]);
    }

    // normalize alphas
    float* ap = out + ALPHA_OFF + ((size_t)b*TT + t)*VV;
    #pragma unroll 1
    for (int v = tid; v < VV; v += 256) ap[v] = __ldcg(&ap[v]) * invS;
    __syncthreads();

    // kc=2 GEMV: rows tid + i*256; same thread consumes in the cell below
    float awe_g[8];
    #pragma unroll 1
    for (int i = 0; i < 8; i++) {
        int row = tid + i*256;
        const __half2* wp = (const __half2*)(g_wz + (size_t)row*KZ + EMBD);
        float a = 0.f;
        #pragma unroll 8
        for (int j = 0; j < 64; j++) {
            float2 f = __half22float2(wp[j]);
            a += f.x*aw[2*j] + f.y*aw[2*j+1];
        }
        awe_g[i] = a;
    }

    // cell: 2 hidden units per thread (rows tid+{0,256,...} map to gates)
    #pragma unroll 1
    for (int jj = 0; jj < 2; jj++) {
        int j = tid + jj*256;
        float g4[4];
        #pragma unroll
        for (int g = 0; g < 4; g++) {
            int row = g*DECD + j;                  // = tid + (2*g+jj)*256
            float s = g_bz[row] + awe_g[2*g + jj];
            #pragma unroll
            for (int kc = 0; kc < NKC; kc++)
                if (kc != 2)
                    s += __ldcg(&g_gpart[((size_t)(kc*BB + b))*NG + row]);
            g4[g] = s;
        }
        int hidx = b*DECD + j;
        float si = sigf(g4[0]), sf = sigf(g4[1]), tg = tanhf(g4[2]), so = sigf(g4[3]);
        float cn = sf * g_c[hidx] + si * tg;
        float hv = so * tanhf(cn);
        g_c[hidx] = cn;
        g_h[hidx] = hv;
        hn[j] = hv;
    }
    __syncthreads();

    // heads(h_new): 413 rows; 2 threads per row (shfl partners share predicate)
    int sub = tid & 1, g = tid >> 1;   // g: 0..127
    #pragma unroll 1
    for (int pass = 0; pass < 4; pass++) {
        int row = pass*128 + g;
        if (row < 413) {
            const float* wrow; float bias; int kind;
            if (row < 256)      { wrow = Wdec  + (size_t)row*DECD;       bias = bdec[row];       kind = 0; }
            else if (row < 384) { wrow = Wbeta + (size_t)(row-256)*DECD; bias = bbeta[row-256];  kind = 1; }
            else                { wrow = Wfin  + (size_t)(row-384)*DECD; bias = bfin[row-384];   kind = 2; }
            float a = 0.f;
            #pragma unroll 8
            for (int i = 0; i < 64; i++) {
                int k = sub*4 + i*8;
                float4 w  = *(const float4*)&wrow[k];
                float4 hz = *(const float4*)&hn[k];
                a += w.x*hz.x + w.y*hz.y + w.z*hz.z + w.w*hz.w;
            }
            a += __shfl_xor_sync(0xffffffffu, a, 1);
            if (sub == 0) {
                a += bias;
                if (kind == 0)      g_dec_att[b*ATTD + row] = a;
                else if (kind == 1) g_gate[b*ENCD + (row-256)] = sigf(a);
                else                out[PRED_OFF + ((size_t)b*TT + t)*NVOC + (row-384)] = a;
            }
        }
    }
}

// ============================================================================
// kB: attention streamer + per-b last-arriver finisher.
// grid(16,64), block 256 = 8 warps.
// ============================================================================
__global__ void __launch_bounds__(256)
kB_atten(int t, const float* __restrict__ wfull, const int* __restrict__ lens,
         const float* __restrict__ Wdec, const float* __restrict__ bdec,
         const float* __restrict__ Wbeta, const float* __restrict__ bbeta,
         const float* __restrict__ Wfin, const float* __restrict__ bfin,
         float* __restrict__ out)
{
    int b = blockIdx.y;
    if (t >= lens[b]) return;
    int tid = threadIdx.x;
    int warp = tid >> 5, l = tid & 31;
    int chunk = blockIdx.x;
    int vbase = chunk*128;

    __shared__ __align__(16) float al[128];
    __shared__ __align__(16) float wred[8];
    __shared__ __align__(16) float red[8*128];
    __shared__ __align__(16) float aw[128];
    __shared__ __align__(16) float hn[512];
    __shared__ int   bc;

    int a0 = l*8;
    __half2 d2[4]; float w[8];
    {
        float4 dd0 = *(const float4*)&g_dec_att[b*ATTD + a0];
        float4 dd1 = *(const float4*)&g_dec_att[b*ATTD + a0 + 4];
        d2[0] = __floats2half2_rn(dd0.x, dd0.y);
        d2[1] = __floats2half2_rn(dd0.z, dd0.w);
        d2[2] = __floats2half2_rn(dd1.x, dd1.y);
        d2[3] = __floats2half2_rn(dd1.z, dd1.w);
        float4 ww0 = *(const float4*)&wfull[a0];
        float4 ww1 = *(const float4*)&wfull[a0 + 4];
        w[0]=ww0.x; w[1]=ww0.y; w[2]=ww0.z; w[3]=ww0.w;
        w[4]=ww1.x; w[5]=ww1.y; w[6]=ww1.z; w[7]=ww1.w;
    }
    const __half2 z2 = __float2half2_rn(0.f);
    const __half* ea = g_enc_att_h + ((size_t)(b*VV + vbase))*ATTD;

    #pragma unroll
    for (int i = 0; i < 16; i += 4) {
        uint4 q[4];
        #pragma unroll
        for (int u = 0; u < 4; u++)
            q[u] = *(const uint4*)&ea[(size_t)((i+u)*8 + warp)*ATTD + a0];
        float s[4];
        #pragma unroll
        for (int u = 0; u < 4; u++) {
            const __half2* hh = (const __half2*)&q[u];
            float acc = 0.f;
            #pragma unroll
            for (int j = 0; j < 4; j++) {
                __half2 v = __hmax2(__hadd2(hh[j], d2[j]), z2);
                float2 f = __half22float2(v);
                acc += f.x*w[2*j] + f.y*w[2*j+1];
            }
            s[u] = acc;
        }
        #pragma unroll
        for (int o = 16; o; o >>= 1) {
            #pragma unroll
            for (int u = 0; u < 4; u++)
                s[u] += __shfl_xor_sync(0xffffffffu, s[u], o);
        }
        if (l == 0) {
            #pragma unroll
            for (int u = 0; u < 4; u++) al[(i+u)*8 + warp] = __expf(s[u]);
        }
    }
    __syncthreads();

    // unnormalized alphas + chunk expsum
    float e = (tid < 128) ? al[tid] : 0.f;
    if (tid < 128) out[ALPHA_OFF + ((size_t)b*TT + t)*VV + vbase + tid] = e;
    #pragma unroll
    for (int o = 16; o; o >>= 1) e += __shfl_xor_sync(0xffffffffu, e, o);
    if (l == 0) wred[warp] = e;

    // partial awe over the chunk's 128 rows
    const __half* eh = g_enc_h + ((size_t)(b*VV + vbase))*ENCD;
    float4 acc = make_float4(0.f,0.f,0.f,0.f);
    #pragma unroll 4
    for (int i = 0; i < 16; i++) {
        int r = i*8 + warp;
        float a = al[r];
        uint2 q = *(const uint2*)&eh[(size_t)r*ENCD + l*4];
        float2 e0 = __half22float2(((const __half2*)&q)[0]);
        float2 e1 = __half22float2(((const __half2*)&q)[1]);
        acc.x += a*e0.x; acc.y += a*e0.y; acc.z += a*e1.x; acc.w += a*e1.y;
    }
    *(float4*)&red[warp*128 + l*4] = acc;
    __syncthreads();
    if (tid < 128) {
        float s = 0.f;
        #pragma unroll
        for (int i = 0; i < 8; i++) s += red[i*128 + tid];
        g_part[(b*NCH + chunk)*ENCD + tid] = s;
    }
    if (tid == 0) {
        float ss = 0.f;
        #pragma unroll
        for (int i = 0; i < 8; i++) ss += wred[i];
        g_psum[b*NCH + chunk] = ss;
    }

    // -------- last-arriver becomes the finisher for b
    __threadfence();
    if (tid == 0) bc = atomicAdd(&g_cnt1[b], 1);
    __syncthreads();
    if (bc != NCH-1) return;
    if (tid == 0) g_cnt1[b] = 0;   // reset for next step / graph replay

    kb_finisher(b, t, tid, Wdec, bdec, Wbeta, bbeta, Wfin, bfin, out, aw, hn);
}

// ============================================================================
extern "C" void kernel_launch(void* const* d_in, const int* in_sizes, int n_in,
                              void* d_out, int out_size)
{
    const float* enc      = (const float*)d_in[0];
    const int*   captions = (const int*)  d_in[1];
    const int*   lens     = (const int*)  d_in[2];
    const float* embW     = (const float*)d_in[3];
    const float* Wenc     = (const float*)d_in[4];
    const float* benc     = (const float*)d_in[5];
    const float* Wdec     = (const float*)d_in[6];
    const float* bdec     = (const float*)d_in[7];
    const float* wfull    = (const float*)d_in[8];
    // d_in[9] = b_full : dropped (softmax shift-invariant)
    const float* Wih      = (const float*)d_in[10];
    const float* bih      = (const float*)d_in[11];
    const float* Whh      = (const float*)d_in[12];
    const float* bhh      = (const float*)d_in[13];
    const float* Winith   = (const float*)d_in[14];
    const float* binith   = (const float*)d_in[15];
    const float* Winitc   = (const float*)d_in[16];
    const float* binitc   = (const float*)d_in[17];
    const float* Wbeta    = (const float*)d_in[18];
    const float* bbeta    = (const float*)d_in[19];
    const float* Wfin     = (const float*)d_in[20];
    const float* bfin     = (const float*)d_in[21];
    float* out = (float*)d_out;

    cudaFuncSetAttribute(s_encatt, cudaFuncAttributeMaxDynamicSharedMemorySize, EA_SMEM);

    cudaMemsetAsync(d_out, 0, (size_t)out_size*sizeof(float), 0);

    s_init<<<BB, 512>>>(enc, lens, Winith, binith, Winitc, binitc,
                        Wdec, bdec, Wbeta, bbeta, out);
    s_wlstm<<<NG, 256>>>(Wih, bih, Whh, bhh);
    s_encatt<<<(BB*VV)/32, 256, EA_SMEM>>>(enc, Wenc, benc);

    for (int t = 0; t < TT; t++) {
        k6a_gemm<<<dim3(6, 32), 256>>>(t, lens, captions, embW);
        kB_atten<<<dim3(NCH, BB), 256>>>(t, wfull, lens,
                                         Wdec, bdec, Wbeta, bbeta,
                                         Wfin, bfin, out);
    }
}

// round 15
// speedup vs baseline: 5.0481x; 5.0481x over previous
#include <cuda_runtime.h>
#include <cuda_fp16.h>
#include <math.h>

#define BB   64
#define VV   2048
#define ENCD 128
#define TT   100
#define EMBD 256
#define DECD 512
#define ATTD 256
#define NVOC 29
#define XD   384   // EMB + ENC
#define NCH  16    // V-chunks of 128
#define NG   2048  // 4*DEC gate rows
#define KZ   896   // XD + DECD
#define NKC  7     // k-chunks of 128

#define PRED_OFF  0
#define ALPHA_OFF (BB*TT*NVOC)            // 185600
#define LEN_OFF   (ALPHA_OFF + BB*TT*VV)  // 13292800

// ---------------- scratch (device globals; no allocation allowed) ----------
__device__ __half g_enc_att_h[BB*VV*ATTD];  // 64 MB fp16
__device__ __half g_enc_h[BB*VV*ENCD];      // 32 MB fp16
__device__ __half g_wz[NG*KZ];              // 3.7 MB merged fp16 [emb|awe|h]
__device__ float  g_bz[NG];                 // merged bias
__device__ float  g_gpart[NKC*BB*NG];       // gate partials [kc][b][row]
__device__ float  g_h[BB*DECD];
__device__ float  g_cbuf[2][BB*DECD];       // ping-pong c (multi-block cell)
__device__ float  g_dec_att[BB*ATTD];
__device__ float  g_gate[BB*ENCD];
__device__ float  g_part[BB*NCH*ENCD];      // partial awe [b][chunk][d]
__device__ float  g_psum[BB*NCH];           // partial expsum

__device__ __forceinline__ float sigf(float x) { return 1.f/(1.f+__expf(-x)); }

// ============================================================================
// Setup A: mean_enc -> h0,c0 ; heads(h0) for step 0 ; lengths to out tail
// ============================================================================
__global__ void s_init(const float* __restrict__ enc, const int* __restrict__ lens,
                       const float* __restrict__ Wih_, const float* __restrict__ bih_,
                       const float* __restrict__ Wic_, const float* __restrict__ bic_,
                       const float* __restrict__ Wdec, const float* __restrict__ bdec,
                       const float* __restrict__ Wbeta, const float* __restrict__ bbeta,
                       float* __restrict__ out)
{
    int b = blockIdx.x, tid = threadIdx.x;
    __shared__ __align__(16) float red[16*128];
    __shared__ __align__(16) float mean[128];
    __shared__ __align__(16) float hs[512];
    int vr = tid >> 5, l = tid & 31;

    float4 acc = make_float4(0.f,0.f,0.f,0.f);
    for (int v = vr; v < VV; v += 16) {
        float4 e = *(const float4*)&enc[((size_t)(b*VV + v))*ENCD + l*4];
        acc.x += e.x; acc.y += e.y; acc.z += e.z; acc.w += e.w;
    }
    *(float4*)&red[vr*128 + l*4] = acc;
    __syncthreads();
    if (tid < 128) {
        float s = 0.f;
        #pragma unroll
        for (int i = 0; i < 16; i++) s += red[i*128 + tid];
        mean[tid] = s * (1.f/(float)VV);
    }
    __syncthreads();
    float ha = bih_[tid], ca = bic_[tid];
    const float* wh = Wih_ + (size_t)tid*ENCD;
    const float* wc = Wic_ + (size_t)tid*ENCD;
    #pragma unroll 4
    for (int k = 0; k < ENCD; k++) {
        float mk = mean[k];
        ha += mk * wh[k];
        ca += mk * wc[k];
    }
    g_h[b*DECD + tid] = ha;
    g_cbuf[0][b*DECD + tid] = ca;
    hs[tid] = ha;
    if (tid == 0) out[LEN_OFF + b] = (float)lens[b];
    __syncthreads();

    int sub = tid & 3, g = tid >> 2;
    #pragma unroll
    for (int pass = 0; pass < 3; pass++) {
        int row = pass*128 + g;
        const float* wrow; float bias; int kind;
        if (row < 256) { wrow = Wdec  + (size_t)row*DECD;       bias = bdec[row];       kind = 0; }
        else           { wrow = Wbeta + (size_t)(row-256)*DECD; bias = bbeta[row-256];  kind = 1; }
        float a = 0.f;
        #pragma unroll 8
        for (int i = 0; i < 32; i++) {
            int k = sub*4 + i*16;
            float4 w  = *(const float4*)&wrow[k];
            float4 hz = *(const float4*)&hs[k];
            a += w.x*hz.x + w.y*hz.y + w.z*hz.z + w.w*hz.w;
        }
        a += __shfl_xor_sync(0xffffffffu, a, 1);
        a += __shfl_xor_sync(0xffffffffu, a, 2);
        if (sub == 0) {
            a += bias;
            if (kind == 0) g_dec_att[b*ATTD + row] = a;
            else           g_gate[b*ENCD + (row-256)] = sigf(a);
        }
    }
}

// ============================================================================
// Setup W: merge LSTM weights to fp16 [row][XD | DECD], merged bias
// ============================================================================
__global__ void s_wlstm(const float* __restrict__ Wih, const float* __restrict__ bih,
                        const float* __restrict__ Whh, const float* __restrict__ bhh)
{
    int row = blockIdx.x, tid = threadIdx.x;
    for (int k = tid; k < XD; k += 256)
        g_wz[(size_t)row*KZ + k] = __float2half_rn(Wih[(size_t)row*XD + k]);
    for (int k = tid; k < DECD; k += 256)
        g_wz[(size_t)row*KZ + XD + k] = __float2half_rn(Whh[(size_t)row*DECD + k]);
    if (tid == 0) g_bz[row] = bih[row] + bhh[row];
}

// ============================================================================
// Setup B: enc_att(fp16) = enc @ W_enc.T + b_enc ; fp16 enc copy
// ============================================================================
#define EA_SMEM ((128*264 + 128*68)*4)
__global__ void __launch_bounds__(256)
s_encatt(const float* __restrict__ enc, const float* __restrict__ Wenc,
         const float* __restrict__ benc)
{
    extern __shared__ float sm[];
    float* Wt = sm;             // [128][264]
    float* Et = sm + 128*264;   // [128][68]
    int tid = threadIdx.x;
    int rowbase = blockIdx.x * 32;

    for (int i = tid; i < 256*128; i += 256) {
        int k = i & 127, a = i >> 7;
        Wt[k*264 + a] = Wenc[a*128 + k];
    }
    for (int i = tid; i < 32*128; i += 256) {
        int k = i & 127, r = i >> 7;
        Et[k*68 + r] = enc[(size_t)(rowbase + r)*128 + k];
    }
    __syncthreads();

    for (int i = tid; i < 32*128; i += 256) {
        int r = i >> 7, k = i & 127;
        g_enc_h[(size_t)(rowbase + r)*ENCD + k] = __float2half_rn(Et[k*68 + r]);
    }

    int tr = tid >> 5, ta = tid & 31;
    int r0 = tr*4, a0 = ta*8;
    float acc[4][8];
    #pragma unroll
    for (int i = 0; i < 4; i++)
        #pragma unroll
        for (int j = 0; j < 8; j++) acc[i][j] = 0.f;

    #pragma unroll 4
    for (int k = 0; k < 128; k++) {
        float4 rf = *(const float4*)&Et[k*68 + r0];
        float4 a4 = *(const float4*)&Wt[k*264 + a0];
        float4 b4 = *(const float4*)&Wt[k*264 + a0 + 4];
        float rr[4] = {rf.x, rf.y, rf.z, rf.w};
        float aa[8] = {a4.x,a4.y,a4.z,a4.w,b4.x,b4.y,b4.z,b4.w};
        #pragma unroll
        for (int i = 0; i < 4; i++)
            #pragma unroll
            for (int j = 0; j < 8; j++) acc[i][j] += rr[i]*aa[j];
    }
    float4 be0 = *(const float4*)&benc[a0];
    float4 be1 = *(const float4*)&benc[a0+4];
    float bb[8] = {be0.x,be0.y,be0.z,be0.w,be1.x,be1.y,be1.z,be1.w};
    #pragma unroll
    for (int i = 0; i < 4; i++) {
        size_t base = (size_t)(rowbase + r0 + i)*ATTD + a0;
        __half2 h[4];
        #pragma unroll
        for (int j = 0; j < 4; j++)
            h[j] = __floats2half2_rn(acc[i][2*j] + bb[2*j], acc[i][2*j+1] + bb[2*j+1]);
        *(uint4*)&g_enc_att_h[base] = *(uint4*)h;
    }
}

// ============================================================================
// kB: attention streamer (exact R9 version — 26us, 51% DRAM, 35 regs).
// grid(16,64), block 256.  Unnormalized alphas to out; partials to globals.
// ============================================================================
__global__ void __launch_bounds__(256)
kB_atten(int t, const float* __restrict__ wfull, const int* __restrict__ lens,
         float* __restrict__ out)
{
    int b = blockIdx.y;
    if (t >= lens[b]) return;
    int tid = threadIdx.x;
    int warp = tid >> 5, l = tid & 31;
    int chunk = blockIdx.x;
    int vbase = chunk*128;

    __shared__ __align__(16) float al[128];
    __shared__ __align__(16) float wred[8];
    __shared__ __align__(16) float red[8*128];

    int a0 = l*8;
    __half2 d2[4]; float w[8];
    {
        float4 dd0 = *(const float4*)&g_dec_att[b*ATTD + a0];
        float4 dd1 = *(const float4*)&g_dec_att[b*ATTD + a0 + 4];
        d2[0] = __floats2half2_rn(dd0.x, dd0.y);
        d2[1] = __floats2half2_rn(dd0.z, dd0.w);
        d2[2] = __floats2half2_rn(dd1.x, dd1.y);
        d2[3] = __floats2half2_rn(dd1.z, dd1.w);
        float4 ww0 = *(const float4*)&wfull[a0];
        float4 ww1 = *(const float4*)&wfull[a0 + 4];
        w[0]=ww0.x; w[1]=ww0.y; w[2]=ww0.z; w[3]=ww0.w;
        w[4]=ww1.x; w[5]=ww1.y; w[6]=ww1.z; w[7]=ww1.w;
    }
    const __half2 z2 = __float2half2_rn(0.f);
    const __half* ea = g_enc_att_h + ((size_t)(b*VV + vbase))*ATTD;

    #pragma unroll
    for (int i = 0; i < 16; i += 4) {
        uint4 q[4];
        #pragma unroll
        for (int u = 0; u < 4; u++)
            q[u] = *(const uint4*)&ea[(size_t)((i+u)*8 + warp)*ATTD + a0];
        float s[4];
        #pragma unroll
        for (int u = 0; u < 4; u++) {
            const __half2* hh = (const __half2*)&q[u];
            float acc = 0.f;
            #pragma unroll
            for (int j = 0; j < 4; j++) {
                __half2 v = __hmax2(__hadd2(hh[j], d2[j]), z2);
                float2 f = __half22float2(v);
                acc += f.x*w[2*j] + f.y*w[2*j+1];
            }
            s[u] = acc;
        }
        #pragma unroll
        for (int o = 16; o; o >>= 1) {
            #pragma unroll
            for (int u = 0; u < 4; u++)
                s[u] += __shfl_xor_sync(0xffffffffu, s[u], o);
        }
        if (l == 0) {
            #pragma unroll
            for (int u = 0; u < 4; u++) al[(i+u)*8 + warp] = __expf(s[u]);
        }
    }
    __syncthreads();

    // unnormalized alphas + chunk expsum
    float e = (tid < 128) ? al[tid] : 0.f;
    if (tid < 128) out[ALPHA_OFF + ((size_t)b*TT + t)*VV + vbase + tid] = e;
    #pragma unroll
    for (int o = 16; o; o >>= 1) e += __shfl_xor_sync(0xffffffffu, e, o);
    if (l == 0) wred[warp] = e;

    // partial awe over the chunk's 128 rows
    const __half* eh = g_enc_h + ((size_t)(b*VV + vbase))*ENCD;
    float4 acc = make_float4(0.f,0.f,0.f,0.f);
    #pragma unroll 4
    for (int i = 0; i < 16; i++) {
        int r = i*8 + warp;
        float a = al[r];
        uint2 q = *(const uint2*)&eh[(size_t)r*ENCD + l*4];
        float2 e0 = __half22float2(((const __half2*)&q)[0]);
        float2 e1 = __half22float2(((const __half2*)&q)[1]);
        acc.x += a*e0.x; acc.y += a*e0.y; acc.z += a*e1.x; acc.w += a*e1.y;
    }
    *(float4*)&red[warp*128 + l*4] = acc;
    __syncthreads();
    if (tid < 128) {
        float s = 0.f;
        #pragma unroll
        for (int i = 0; i < 8; i++) s += red[i*128 + tid];
        g_part[(b*NCH + chunk)*ENCD + tid] = s;
    }
    if (tid == 0) {
        float ss = 0.f;
        #pragma unroll
        for (int i = 0; i < 8; i++) ss += wred[i];
        g_psum[b*NCH + chunk] = ss;
    }
}

// ============================================================================
// k6a: split-K LSTM GEMM, occupancy-fixed.  grid(7, 64), block 256.
// 32-row chunks, fp16 smem tiles (~27KB vs 70KB) -> 448 blocks, better latency
// hiding.  kc 0,1: z=emb ; kc 2: z=awe (combine partials) ; kc 3..6: z=h.
// ============================================================================
__global__ void __launch_bounds__(256)
k6a_gemm(int t, const int* __restrict__ lens,
         const int* __restrict__ captions, const float* __restrict__ embW)
{
    int kc = blockIdx.x, rc = blockIdx.y, tid = threadIdx.x;
    __shared__ __align__(16) __half wt[128*40];   // [k][32r pad40]  10 KB
    __shared__ __align__(16) __half zt[128*66];   // [k][64b pad66]  16.9 KB
    __shared__ float invs[64];
    __shared__ int   caps[64];

    int pred = (tid < 64) && (t < lens[tid]);
    int nb = __syncthreads_count(pred);   // active prefix (lens sorted desc)
    if (nb == 0) return;

    int kbase = kc * 128;
    int rowbase = rc * 32;

    if (kc == 2 && tid < 64) {
        float s = 0.f;
        #pragma unroll
        for (int r = 0; r < NCH; r++) s += g_psum[tid*NCH + r];
        invs[tid] = 1.f/s;
    }
    if (kc < 2 && tid < 64) caps[tid] = captions[tid*TT + t];
    __syncthreads();

    // weight tile: 32 rows x 128 k (half2 along k, scatter to [k][r])
    for (int i = tid; i < 32*64; i += 256) {
        int r = i >> 6, kp = i & 63;
        __half2 u = *(const __half2*)&g_wz[(size_t)(rowbase + r)*KZ + kbase + kp*2];
        wt[(kp*2  )*40 + r] = __low2half(u);
        wt[(kp*2+1)*40 + r] = __high2half(u);
    }
    // z tile [k][b] in fp16
    if (kc < 2) {
        for (int i = tid; i < 64*128; i += 256) {
            int b = i >> 7, k = i & 127;
            zt[k*66 + b] = __float2half_rn(embW[(size_t)caps[b]*EMBD + kbase + k]);
        }
    } else if (kc == 2) {
        for (int i = tid; i < 64*128; i += 256) {
            int b = i >> 7, d = i & 127;
            float s = 0.f;
            #pragma unroll
            for (int r = 0; r < NCH; r++) s += g_part[(b*NCH + r)*ENCD + d];
            zt[d*66 + b] = __float2half_rn(s * invs[b] * g_gate[b*ENCD + d]);
        }
    } else {
        for (int i = tid; i < 64*128; i += 256) {
            int b = i >> 7, k = i & 127;
            zt[k*66 + b] = __float2half_rn(g_h[b*DECD + (kbase - XD) + k]);
        }
    }
    __syncthreads();

    int r0 = (tid & 7) * 4;     // 8 row-groups of 4
    int b0 = (tid >> 3) * 2;    // 32 b-groups of 2
    if (b0 >= nb) return;

    float acc[4][2];
    #pragma unroll
    for (int i = 0; i < 4; i++) { acc[i][0] = 0.f; acc[i][1] = 0.f; }

    #pragma unroll 4
    for (int k = 0; k < 128; k++) {
        float2 w01 = __half22float2(*(const __half2*)&wt[k*40 + r0]);
        float2 w23 = __half22float2(*(const __half2*)&wt[k*40 + r0 + 2]);
        float2 zz  = __half22float2(*(const __half2*)&zt[k*66 + b0]);
        acc[0][0] += w01.x*zz.x; acc[0][1] += w01.x*zz.y;
        acc[1][0] += w01.y*zz.x; acc[1][1] += w01.y*zz.y;
        acc[2][0] += w23.x*zz.x; acc[2][1] += w23.x*zz.y;
        acc[3][0] += w23.y*zz.x; acc[3][1] += w23.y*zz.y;
    }
    #pragma unroll
    for (int j = 0; j < 2; j++) {
        *(float4*)&g_gpart[((size_t)(kc*BB + b0 + j))*NG + rowbase + r0] =
            make_float4(acc[0][j], acc[1][j], acc[2][j], acc[3][j]);
    }
}

// ============================================================================
// k6b: cell + heads + alpha-normalize.  grid(64, 4), block(512).  (R9 exact)
// ============================================================================
__global__ void __launch_bounds__(512)
k6b_cell(int t, const int* __restrict__ lens,
         const float* __restrict__ Wdec, const float* __restrict__ bdec,
         const float* __restrict__ Wbeta, const float* __restrict__ bbeta,
         const float* __restrict__ Wfin, const float* __restrict__ bfin,
         float* __restrict__ out)
{
    int b = blockIdx.x;
    if (t >= lens[b]) return;
    int by = blockIdx.y;
    int tid = threadIdx.x;
    __shared__ __align__(16) float hn[512];
    __shared__ float ps[NCH];

    if (tid < NCH) ps[tid] = g_psum[b*NCH + tid];

    float g4[4];
    #pragma unroll
    for (int g = 0; g < 4; g++) {
        int row = g*DECD + tid;
        float s = g_bz[row];
        #pragma unroll
        for (int kc = 0; kc < NKC; kc++)
            s += g_gpart[((size_t)(kc*BB + b))*NG + row];
        g4[g] = s;
    }
    int hidx = b*DECD + tid;
    int p = t & 1;
    float si = sigf(g4[0]), sf = sigf(g4[1]), tg = tanhf(g4[2]), so = sigf(g4[3]);
    float cn = sf * g_cbuf[p][hidx] + si * tg;
    float hv = so * tanhf(cn);
    if (by == 0) { g_cbuf[1-p][hidx] = cn; g_h[hidx] = hv; }
    hn[tid] = hv;
    __syncthreads();

    float S = 0.f;
    #pragma unroll
    for (int i = 0; i < NCH; i++) S += ps[i];
    float invS = 1.f/S;
    out[ALPHA_OFF + ((size_t)b*TT + t)*VV + by*512 + tid] *= invS;

    int sub = tid & 3, g = tid >> 2;   // g: 0..127
    int row = by*104 + g;
    if (g < 104 && row < 413) {
        const float* wrow; float bias; int kind;
        if (row < 256)      { wrow = Wdec  + (size_t)row*DECD;       bias = bdec[row];       kind = 0; }
        else if (row < 384) { wrow = Wbeta + (size_t)(row-256)*DECD; bias = bbeta[row-256];  kind = 1; }
        else                { wrow = Wfin  + (size_t)(row-384)*DECD; bias = bfin[row-384];   kind = 2; }
        float a = 0.f;
        #pragma unroll 8
        for (int i = 0; i < 32; i++) {
            int k = sub*4 + i*16;
            float4 w  = *(const float4*)&wrow[k];
            float4 hz = *(const float4*)&hn[k];
            a += w.x*hz.x + w.y*hz.y + w.z*hz.z + w.w*hz.w;
        }
        a += __shfl_xor_sync(0xffffffffu, a, 1);
        a += __shfl_xor_sync(0xffffffffu, a, 2);
        if (sub == 0) {
            a += bias;
            if (kind == 0)      g_dec_att[b*ATTD + row] = a;
            else if (kind == 1) g_gate[b*ENCD + (row-256)] = sigf(a);
            else                out[PRED_OFF + ((size_t)b*TT + t)*NVOC + (row-384)] = a;
        }
    }
}

// ============================================================================
extern "C" void kernel_launch(void* const* d_in, const int* in_sizes, int n_in,
                              void* d_out, int out_size)
{
    const float* enc      = (const float*)d_in[0];
    const int*   captions = (const int*)  d_in[1];
    const int*   lens     = (const int*)  d_in[2];
    const float* embW     = (const float*)d_in[3];
    const float* Wenc     = (const float*)d_in[4];
    const float* benc     = (const float*)d_in[5];
    const float* Wdec     = (const float*)d_in[6];
    const float* bdec     = (const float*)d_in[7];
    const float* wfull    = (const float*)d_in[8];
    // d_in[9] = b_full : dropped (softmax shift-invariant)
    const float* Wih      = (const float*)d_in[10];
    const float* bih      = (const float*)d_in[11];
    const float* Whh      = (const float*)d_in[12];
    const float* bhh      = (const float*)d_in[13];
    const float* Winith   = (const float*)d_in[14];
    const float* binith   = (const float*)d_in[15];
    const float* Winitc   = (const float*)d_in[16];
    const float* binitc   = (const float*)d_in[17];
    const float* Wbeta    = (const float*)d_in[18];
    const float* bbeta    = (const float*)d_in[19];
    const float* Wfin     = (const float*)d_in[20];
    const float* bfin     = (const float*)d_in[21];
    float* out = (float*)d_out;

    cudaFuncSetAttribute(s_encatt, cudaFuncAttributeMaxDynamicSharedMemorySize, EA_SMEM);

    cudaMemsetAsync(d_out, 0, (size_t)out_size*sizeof(float), 0);

    s_init<<<BB, 512>>>(enc, lens, Winith, binith, Winitc, binitc,
                        Wdec, bdec, Wbeta, bbeta, out);
    s_wlstm<<<NG, 256>>>(Wih, bih, Whh, bhh);
    s_encatt<<<(BB*VV)/32, 256, EA_SMEM>>>(enc, Wenc, benc);

    for (int t = 0; t < TT; t++) {
        kB_atten<<<dim3(NCH, BB), 256>>>(t, wfull, lens, out);
        k6a_gemm<<<dim3(NKC, 64), 256>>>(t, lens, captions, embW);
        k6b_cell<<<dim3(BB, 4), 512>>>(t, lens, Wdec, bdec, Wbeta, bbeta,
                                       Wfin, bfin, out);
    }
}

// round 16
// speedup vs baseline: 5.6329x; 1.1159x over previous
#include <cuda_runtime.h>
#include <cuda_fp16.h>
#include <math.h>

#define BB   64
#define VV   2048
#define ENCD 128
#define TT   100
#define EMBD 256
#define DECD 512
#define ATTD 256
#define NVOC 29
#define XD   384   // EMB + ENC
#define NCH  16    // V-chunks of 128
#define NG   2048  // 4*DEC gate rows
#define KZ   896   // XD + DECD
#define NKC  7     // k-chunks of 128

#define PRED_OFF  0
#define ALPHA_OFF (BB*TT*NVOC)            // 185600
#define LEN_OFF   (ALPHA_OFF + BB*TT*VV)  // 13292800

// ---------------- scratch (device globals; no allocation allowed) ----------
__device__ __half g_enc_att_h[BB*VV*ATTD];  // 64 MB fp16
__device__ __half g_enc_h[BB*VV*ENCD];      // 32 MB fp16
__device__ __half g_wz[NG*KZ];              // 3.7 MB merged fp16 [emb|awe|h]
__device__ float  g_bz[NG];                 // merged bias
__device__ float  g_gpart[NKC*BB*NG];       // gate partials [kc][b][row]
__device__ float  g_h[BB*DECD];
__device__ float  g_cbuf[2][BB*DECD];       // ping-pong c (multi-block cell)
__device__ float  g_dec_att[BB*ATTD];
__device__ float  g_gate[BB*ENCD];
__device__ float  g_part[BB*NCH*ENCD];      // partial awe [b][chunk][d]
__device__ float  g_psum[BB*NCH];           // partial expsum

__device__ __forceinline__ float sigf(float x) { return 1.f/(1.f+__expf(-x)); }

// ============================================================================
// Setup A: mean_enc -> h0,c0 ; heads(h0) for step 0 ; lengths to out tail
// ============================================================================
__global__ void s_init(const float* __restrict__ enc, const int* __restrict__ lens,
                       const float* __restrict__ Wih_, const float* __restrict__ bih_,
                       const float* __restrict__ Wic_, const float* __restrict__ bic_,
                       const float* __restrict__ Wdec, const float* __restrict__ bdec,
                       const float* __restrict__ Wbeta, const float* __restrict__ bbeta,
                       float* __restrict__ out)
{
    int b = blockIdx.x, tid = threadIdx.x;
    __shared__ __align__(16) float red[16*128];
    __shared__ __align__(16) float mean[128];
    __shared__ __align__(16) float hs[512];
    int vr = tid >> 5, l = tid & 31;

    float4 acc = make_float4(0.f,0.f,0.f,0.f);
    for (int v = vr; v < VV; v += 16) {
        float4 e = *(const float4*)&enc[((size_t)(b*VV + v))*ENCD + l*4];
        acc.x += e.x; acc.y += e.y; acc.z += e.z; acc.w += e.w;
    }
    *(float4*)&red[vr*128 + l*4] = acc;
    __syncthreads();
    if (tid < 128) {
        float s = 0.f;
        #pragma unroll
        for (int i = 0; i < 16; i++) s += red[i*128 + tid];
        mean[tid] = s * (1.f/(float)VV);
    }
    __syncthreads();
    float ha = bih_[tid], ca = bic_[tid];
    const float* wh = Wih_ + (size_t)tid*ENCD;
    const float* wc = Wic_ + (size_t)tid*ENCD;
    #pragma unroll 4
    for (int k = 0; k < ENCD; k++) {
        float mk = mean[k];
        ha += mk * wh[k];
        ca += mk * wc[k];
    }
    g_h[b*DECD + tid] = ha;
    g_cbuf[0][b*DECD + tid] = ca;
    hs[tid] = ha;
    if (tid == 0) out[LEN_OFF + b] = (float)lens[b];
    __syncthreads();

    int sub = tid & 3, g = tid >> 2;
    #pragma unroll
    for (int pass = 0; pass < 3; pass++) {
        int row = pass*128 + g;
        const float* wrow; float bias; int kind;
        if (row < 256) { wrow = Wdec  + (size_t)row*DECD;       bias = bdec[row];       kind = 0; }
        else           { wrow = Wbeta + (size_t)(row-256)*DECD; bias = bbeta[row-256];  kind = 1; }
        float a = 0.f;
        #pragma unroll 8
        for (int i = 0; i < 32; i++) {
            int k = sub*4 + i*16;
            float4 w  = *(const float4*)&wrow[k];
            float4 hz = *(const float4*)&hs[k];
            a += w.x*hz.x + w.y*hz.y + w.z*hz.z + w.w*hz.w;
        }
        a += __shfl_xor_sync(0xffffffffu, a, 1);
        a += __shfl_xor_sync(0xffffffffu, a, 2);
        if (sub == 0) {
            a += bias;
            if (kind == 0) g_dec_att[b*ATTD + row] = a;
            else           g_gate[b*ENCD + (row-256)] = sigf(a);
        }
    }
}

// ============================================================================
// Setup W: merge LSTM weights to fp16 [row][XD | DECD], merged bias
// ============================================================================
__global__ void s_wlstm(const float* __restrict__ Wih, const float* __restrict__ bih,
                        const float* __restrict__ Whh, const float* __restrict__ bhh)
{
    int row = blockIdx.x, tid = threadIdx.x;
    for (int k = tid; k < XD; k += 256)
        g_wz[(size_t)row*KZ + k] = __float2half_rn(Wih[(size_t)row*XD + k]);
    for (int k = tid; k < DECD; k += 256)
        g_wz[(size_t)row*KZ + XD + k] = __float2half_rn(Whh[(size_t)row*DECD + k]);
    if (tid == 0) g_bz[row] = bih[row] + bhh[row];
}

// ============================================================================
// Setup B: enc_att(fp16) = enc @ W_enc.T + b_enc ; fp16 enc copy
// ============================================================================
#define EA_SMEM ((128*264 + 128*68)*4)
__global__ void __launch_bounds__(256)
s_encatt(const float* __restrict__ enc, const float* __restrict__ Wenc,
         const float* __restrict__ benc)
{
    extern __shared__ float sm[];
    float* Wt = sm;             // [128][264]
    float* Et = sm + 128*264;   // [128][68]
    int tid = threadIdx.x;
    int rowbase = blockIdx.x * 32;

    for (int i = tid; i < 256*128; i += 256) {
        int k = i & 127, a = i >> 7;
        Wt[k*264 + a] = Wenc[a*128 + k];
    }
    for (int i = tid; i < 32*128; i += 256) {
        int k = i & 127, r = i >> 7;
        Et[k*68 + r] = enc[(size_t)(rowbase + r)*128 + k];
    }
    __syncthreads();

    for (int i = tid; i < 32*128; i += 256) {
        int r = i >> 7, k = i & 127;
        g_enc_h[(size_t)(rowbase + r)*ENCD + k] = __float2half_rn(Et[k*68 + r]);
    }

    int tr = tid >> 5, ta = tid & 31;
    int r0 = tr*4, a0 = ta*8;
    float acc[4][8];
    #pragma unroll
    for (int i = 0; i < 4; i++)
        #pragma unroll
        for (int j = 0; j < 8; j++) acc[i][j] = 0.f;

    #pragma unroll 4
    for (int k = 0; k < 128; k++) {
        float4 rf = *(const float4*)&Et[k*68 + r0];
        float4 a4 = *(const float4*)&Wt[k*264 + a0];
        float4 b4 = *(const float4*)&Wt[k*264 + a0 + 4];
        float rr[4] = {rf.x, rf.y, rf.z, rf.w};
        float aa[8] = {a4.x,a4.y,a4.z,a4.w,b4.x,b4.y,b4.z,b4.w};
        #pragma unroll
        for (int i = 0; i < 4; i++)
            #pragma unroll
            for (int j = 0; j < 8; j++) acc[i][j] += rr[i]*aa[j];
    }
    float4 be0 = *(const float4*)&benc[a0];
    float4 be1 = *(const float4*)&benc[a0+4];
    float bb[8] = {be0.x,be0.y,be0.z,be0.w,be1.x,be1.y,be1.z,be1.w};
    #pragma unroll
    for (int i = 0; i < 4; i++) {
        size_t base = (size_t)(rowbase + r0 + i)*ATTD + a0;
        __half2 h[4];
        #pragma unroll
        for (int j = 0; j < 4; j++)
            h[j] = __floats2half2_rn(acc[i][2*j] + bb[2*j], acc[i][2*j+1] + bb[2*j+1]);
        *(uint4*)&g_enc_att_h[base] = *(uint4*)h;
    }
}

// ============================================================================
// kB: attention streamer (R9 exact) + PDL sync before dependent reads.
// grid(16,64), block 256.
// ============================================================================
__global__ void __launch_bounds__(256)
kB_atten(int t, const float* __restrict__ wfull, const int* __restrict__ lens,
         float* __restrict__ out)
{
    int b = blockIdx.y;
    if (t >= lens[b]) return;          // lens is an input: safe pre-sync
    int tid = threadIdx.x;
    int warp = tid >> 5, l = tid & 31;
    int chunk = blockIdx.x;
    int vbase = chunk*128;

    __shared__ __align__(16) float al[128];
    __shared__ __align__(16) float wred[8];
    __shared__ __align__(16) float red[8*128];

    cudaGridDependencySynchronize();   // k6b(t-1) wrote g_dec_att / g_gate

    int a0 = l*8;
    __half2 d2[4]; float w[8];
    {
        float4 dd0 = *(const float4*)&g_dec_att[b*ATTD + a0];
        float4 dd1 = *(const float4*)&g_dec_att[b*ATTD + a0 + 4];
        d2[0] = __floats2half2_rn(dd0.x, dd0.y);
        d2[1] = __floats2half2_rn(dd0.z, dd0.w);
        d2[2] = __floats2half2_rn(dd1.x, dd1.y);
        d2[3] = __floats2half2_rn(dd1.z, dd1.w);
        float4 ww0 = *(const float4*)&wfull[a0];
        float4 ww1 = *(const float4*)&wfull[a0 + 4];
        w[0]=ww0.x; w[1]=ww0.y; w[2]=ww0.z; w[3]=ww0.w;
        w[4]=ww1.x; w[5]=ww1.y; w[6]=ww1.z; w[7]=ww1.w;
    }
    const __half2 z2 = __float2half2_rn(0.f);
    const __half* ea = g_enc_att_h + ((size_t)(b*VV + vbase))*ATTD;

    #pragma unroll
    for (int i = 0; i < 16; i += 4) {
        uint4 q[4];
        #pragma unroll
        for (int u = 0; u < 4; u++)
            q[u] = *(const uint4*)&ea[(size_t)((i+u)*8 + warp)*ATTD + a0];
        float s[4];
        #pragma unroll
        for (int u = 0; u < 4; u++) {
            const __half2* hh = (const __half2*)&q[u];
            float acc = 0.f;
            #pragma unroll
            for (int j = 0; j < 4; j++) {
                __half2 v = __hmax2(__hadd2(hh[j], d2[j]), z2);
                float2 f = __half22float2(v);
                acc += f.x*w[2*j] + f.y*w[2*j+1];
            }
            s[u] = acc;
        }
        #pragma unroll
        for (int o = 16; o; o >>= 1) {
            #pragma unroll
            for (int u = 0; u < 4; u++)
                s[u] += __shfl_xor_sync(0xffffffffu, s[u], o);
        }
        if (l == 0) {
            #pragma unroll
            for (int u = 0; u < 4; u++) al[(i+u)*8 + warp] = __expf(s[u]);
        }
    }
    __syncthreads();

    // unnormalized alphas + chunk expsum
    float e = (tid < 128) ? al[tid] : 0.f;
    if (tid < 128) out[ALPHA_OFF + ((size_t)b*TT + t)*VV + vbase + tid] = e;
    #pragma unroll
    for (int o = 16; o; o >>= 1) e += __shfl_xor_sync(0xffffffffu, e, o);
    if (l == 0) wred[warp] = e;

    // partial awe over the chunk's 128 rows
    const __half* eh = g_enc_h + ((size_t)(b*VV + vbase))*ENCD;
    float4 acc = make_float4(0.f,0.f,0.f,0.f);
    #pragma unroll 4
    for (int i = 0; i < 16; i++) {
        int r = i*8 + warp;
        float a = al[r];
        uint2 q = *(const uint2*)&eh[(size_t)r*ENCD + l*4];
        float2 e0 = __half22float2(((const __half2*)&q)[0]);
        float2 e1 = __half22float2(((const __half2*)&q)[1]);
        acc.x += a*e0.x; acc.y += a*e0.y; acc.z += a*e1.x; acc.w += a*e1.y;
    }
    *(float4*)&red[warp*128 + l*4] = acc;
    __syncthreads();
    if (tid < 128) {
        float s = 0.f;
        #pragma unroll
        for (int i = 0; i < 8; i++) s += red[i*128 + tid];
        g_part[(b*NCH + chunk)*ENCD + tid] = s;
    }
    if (tid == 0) {
        float ss = 0.f;
        #pragma unroll
        for (int i = 0; i < 8; i++) ss += wred[i];
        g_psum[b*NCH + chunk] = ss;
    }
}

// ============================================================================
// k6a: split-K LSTM GEMM (R9 exact: fp32 tiles, grid(7,32)) + PDL.
// Weight tile loads (setup-constant g_wz) overlap kB via PDL prologue;
// gridDepSync before any read of g_psum/g_part/g_gate (kB) or g_h (k6b(t-1)).
// ============================================================================
__global__ void __launch_bounds__(256)
k6a_gemm(int t, const int* __restrict__ lens,
         const int* __restrict__ captions, const float* __restrict__ embW)
{
    int kc = blockIdx.x, rc = blockIdx.y, tid = threadIdx.x;
    __shared__ __align__(16) float wt[128*68];   // [k][r]
    __shared__ __align__(16) float zt[128*68];   // [k][b]
    __shared__ float invs[64];
    __shared__ int   caps[64];

    int pred = (tid < 64) && (t < lens[tid]);    // lens: input, safe
    int nb = __syncthreads_count(pred);
    if (nb == 0) { cudaGridDependencySynchronize(); return; }

    int kbase = kc * 128;
    int rowbase = rc * 64;

    if (kc < 2 && tid < 64) caps[tid] = captions[tid*TT + t];   // input, safe

    // ---- prologue (independent of kB): weight tile from setup-constant g_wz
    for (int i = tid; i < 64*64; i += 256) {
        int r = i >> 6, kp = i & 63;
        unsigned int u = *(const unsigned int*)&g_wz[(size_t)(rowbase + r)*KZ + kbase + kp*2];
        float2 f = __half22float2(*(const __half2*)&u);
        wt[(kp*2  )*68 + r] = f.x;
        wt[(kp*2+1)*68 + r] = f.y;
    }

    cudaGridDependencySynchronize();   // kB done => g_psum/g_part valid;
                                       // transitively k6b(t-1) done => g_h valid

    if (kc == 2 && tid < 64) {
        float s = 0.f;
        #pragma unroll
        for (int r = 0; r < NCH; r++) s += g_psum[tid*NCH + r];
        invs[tid] = 1.f/s;
    }
    __syncthreads();

    // z tile [k][b]
    if (kc < 2) {
        for (int i = tid; i < 64*128; i += 256) {
            int b = i >> 7, k = i & 127;
            zt[k*68 + b] = embW[(size_t)caps[b]*EMBD + kbase + k];
        }
    } else if (kc == 2) {
        for (int i = tid; i < 64*128; i += 256) {
            int b = i >> 7, d = i & 127;
            float s = 0.f;
            #pragma unroll
            for (int r = 0; r < NCH; r++) s += g_part[(b*NCH + r)*ENCD + d];
            zt[d*68 + b] = s * invs[b] * g_gate[b*ENCD + d];
        }
    } else {
        for (int i = tid; i < 64*128; i += 256) {
            int b = i >> 7, k = i & 127;
            zt[k*68 + b] = g_h[b*DECD + (kbase - XD) + k];
        }
    }
    __syncthreads();

    int r0 = (tid & 15) * 4;
    int b0 = (tid >> 4) * 4;
    if (b0 >= nb) return;

    float acc[4][4];
    #pragma unroll
    for (int i = 0; i < 4; i++)
        #pragma unroll
        for (int j = 0; j < 4; j++) acc[i][j] = 0.f;

    #pragma unroll 4
    for (int k = 0; k < 128; k++) {
        float4 w = *(const float4*)&wt[k*68 + r0];
        float4 z = *(const float4*)&zt[k*68 + b0];
        float ww[4] = {w.x, w.y, w.z, w.w};
        float zz[4] = {z.x, z.y, z.z, z.w};
        #pragma unroll
        for (int i = 0; i < 4; i++)
            #pragma unroll
            for (int j = 0; j < 4; j++) acc[i][j] += ww[i]*zz[j];
    }
    #pragma unroll
    for (int j = 0; j < 4; j++) {
        *(float4*)&g_gpart[((size_t)(kc*BB + b0 + j))*NG + rowbase + r0] =
            make_float4(acc[0][j], acc[1][j], acc[2][j], acc[3][j]);
    }
}

// ============================================================================
// k6b: cell + heads + alpha-normalize (R9 exact) + PDL sync at start.
// grid(64, 4), block(512).
// ============================================================================
__global__ void __launch_bounds__(512)
k6b_cell(int t, const int* __restrict__ lens,
         const float* __restrict__ Wdec, const float* __restrict__ bdec,
         const float* __restrict__ Wbeta, const float* __restrict__ bbeta,
         const float* __restrict__ Wfin, const float* __restrict__ bfin,
         float* __restrict__ out)
{
    int b = blockIdx.x;
    if (t >= lens[b]) return;          // input-only read: safe pre-sync
    int by = blockIdx.y;
    int tid = threadIdx.x;
    __shared__ __align__(16) float hn[512];
    __shared__ float ps[NCH];

    cudaGridDependencySynchronize();   // k6a done (=> kB done transitively)

    if (tid < NCH) ps[tid] = g_psum[b*NCH + tid];

    float g4[4];
    #pragma unroll
    for (int g = 0; g < 4; g++) {
        int row = g*DECD + tid;
        float s = g_bz[row];
        #pragma unroll
        for (int kc = 0; kc < NKC; kc++)
            s += g_gpart[((size_t)(kc*BB + b))*NG + row];
        g4[g] = s;
    }
    int hidx = b*DECD + tid;
    int p = t & 1;
    float si = sigf(g4[0]), sf = sigf(g4[1]), tg = tanhf(g4[2]), so = sigf(g4[3]);
    float cn = sf * g_cbuf[p][hidx] + si * tg;
    float hv = so * tanhf(cn);
    if (by == 0) { g_cbuf[1-p][hidx] = cn; g_h[hidx] = hv; }
    hn[tid] = hv;
    __syncthreads();

    float S = 0.f;
    #pragma unroll
    for (int i = 0; i < NCH; i++) S += ps[i];
    float invS = 1.f/S;
    out[ALPHA_OFF + ((size_t)b*TT + t)*VV + by*512 + tid] *= invS;

    int sub = tid & 3, g = tid >> 2;   // g: 0..127
    int row = by*104 + g;
    if (g < 104 && row < 413) {
        const float* wrow; float bias; int kind;
        if (row < 256)      { wrow = Wdec  + (size_t)row*DECD;       bias = bdec[row];       kind = 0; }
        else if (row < 384) { wrow = Wbeta + (size_t)(row-256)*DECD; bias = bbeta[row-256];  kind = 1; }
        else                { wrow = Wfin  + (size_t)(row-384)*DECD; bias = bfin[row-384];   kind = 2; }
        float a = 0.f;
        #pragma unroll 8
        for (int i = 0; i < 32; i++) {
            int k = sub*4 + i*16;
            float4 w  = *(const float4*)&wrow[k];
            float4 hz = *(const float4*)&hn[k];
            a += w.x*hz.x + w.y*hz.y + w.z*hz.z + w.w*hz.w;
        }
        a += __shfl_xor_sync(0xffffffffu, a, 1);
        a += __shfl_xor_sync(0xffffffffu, a, 2);
        if (sub == 0) {
            a += bias;
            if (kind == 0)      g_dec_att[b*ATTD + row] = a;
            else if (kind == 1) g_gate[b*ENCD + (row-256)] = sigf(a);
            else                out[PRED_OFF + ((size_t)b*TT + t)*NVOC + (row-384)] = a;
        }
    }
}

// ============================================================================
extern "C" void kernel_launch(void* const* d_in, const int* in_sizes, int n_in,
                              void* d_out, int out_size)
{
    const float* enc      = (const float*)d_in[0];
    const int*   captions = (const int*)  d_in[1];
    const int*   lens     = (const int*)  d_in[2];
    const float* embW     = (const float*)d_in[3];
    const float* Wenc     = (const float*)d_in[4];
    const float* benc     = (const float*)d_in[5];
    const float* Wdec     = (const float*)d_in[6];
    const float* bdec     = (const float*)d_in[7];
    const float* wfull    = (const float*)d_in[8];
    // d_in[9] = b_full : dropped (softmax shift-invariant)
    const float* Wih      = (const float*)d_in[10];
    const float* bih      = (const float*)d_in[11];
    const float* Whh      = (const float*)d_in[12];
    const float* bhh      = (const float*)d_in[13];
    const float* Winith   = (const float*)d_in[14];
    const float* binith   = (const float*)d_in[15];
    const float* Winitc   = (const float*)d_in[16];
    const float* binitc   = (const float*)d_in[17];
    const float* Wbeta    = (const float*)d_in[18];
    const float* bbeta    = (const float*)d_in[19];
    const float* Wfin     = (const float*)d_in[20];
    const float* bfin     = (const float*)d_in[21];
    float* out = (float*)d_out;

    cudaFuncSetAttribute(s_encatt, cudaFuncAttributeMaxDynamicSharedMemorySize, EA_SMEM);

    cudaMemsetAsync(d_out, 0, (size_t)out_size*sizeof(float), 0);

    s_init<<<BB, 512>>>(enc, lens, Winith, binith, Winitc, binitc,
                        Wdec, bdec, Wbeta, bbeta, out);
    s_wlstm<<<NG, 256>>>(Wih, bih, Whh, bhh);
    s_encatt<<<(BB*VV)/32, 256, EA_SMEM>>>(enc, Wenc, benc);

    // PDL launch configs (no allocation: stack structs, default stream)
    cudaLaunchAttribute pdlAttr;
    pdlAttr.id = cudaLaunchAttributeProgrammaticStreamSerialization;
    pdlAttr.val.programmaticStreamSerializationAllowed = 1;

    cudaLaunchConfig_t cfgB = {};
    cfgB.gridDim = dim3(NCH, BB); cfgB.blockDim = dim3(256);
    cfgB.stream = 0; cfgB.attrs = &pdlAttr; cfgB.numAttrs = 1;

    cudaLaunchConfig_t cfgA = {};
    cfgA.gridDim = dim3(NKC, 32); cfgA.blockDim = dim3(256);
    cfgA.stream = 0; cfgA.attrs = &pdlAttr; cfgA.numAttrs = 1;

    cudaLaunchConfig_t cfgC = {};
    cfgC.gridDim = dim3(BB, 4); cfgC.blockDim = dim3(512);
    cfgC.stream = 0; cfgC.attrs = &pdlAttr; cfgC.numAttrs = 1;

    for (int t = 0; t < TT; t++) {
        cudaLaunchKernelEx(&cfgB, kB_atten, t, wfull, lens, out);
        cudaLaunchKernelEx(&cfgA, k6a_gemm, t, lens, captions, embW);
        cudaLaunchKernelEx(&cfgC, k6b_cell, t, lens, Wdec, bdec, Wbeta, bbeta,
                           Wfin, bfin, out);
    }
}